// round 9
// baseline (speedup 1.0000x reference)
#include <cuda_runtime.h>

// P1 vector FEM eval on structured 16x16 triangulated unit square.
// Bit-faithful numerics (R4): exact fp32 classification, interior-gridline
// bbox exclusion, argmax tie -> upper triangle, reference op-order output.
//
// Perf (R9 = R4 geometry + R5 smem): 256 CTAs x 256 threads, 1 point/thread
// (2048 warps total -- max latency hiding; warp count, not bytes/thread, has
// tracked kernel dur across R4-R8), weights staged in smem as interleaved
// (wx,wy) float2 pairs via float4 fill (73 active fill threads, fast bar
// release); each vertex gather is one conflict-free LDS.64 broadcast.

__device__ __forceinline__ void eval_point(
    float px, float py, const float2* __restrict__ w, float& ox, float& oy)
{
    const float NTOL = -1e-10f;

    float fx = __fmul_rn(px, 16.0f);    // exact
    float fy = __fmul_rn(py, 16.0f);
    int i = (int)floorf(fx);
    int j = (int)floorf(fy);
    i = min(max(i, 0), 15);
    j = min(max(j, 0), 15);

    float u = __fsub_rn(fx, (float)i);  // exact
    float v = __fsub_rn(fy, (float)j);  // exact

    // reference-faithful inside tests (exact fp32)
    float P  = __fsub_rn(fx, fy);                 // fl(16px - 16py)
    float s1 = __fsub_rn(P, (float)(i - j));      // T1 s
    float t2 = -s1;                               // T2 t (bitwise)

    bool in1 = (s1 > NTOL) && (v > NTOL) && (__fadd_rn(s1, v) < 1.0f);
    bool in2 = (u  > NTOL) && (t2 > NTOL) && (__fadd_rn(u, t2) < 1.0f);

    // interior gridline points fail every strict bbox in the reference
    bool on_g = ((u == 0.0f) && (i > 0)) || ((v == 0.0f) && (j > 0));
    bool hit = (px >= 0.0f) && (px < 1.0f) && (py >= 0.0f) && (py < 1.0f) &&
               !on_g && (in1 || in2);

    // branchless triangle select (argmax tie -> T2)
    int v00 = i * 17 + j;
    float s  = in2 ? u : __fsub_rn(u, v);
    float t  = in2 ? __fsub_rn(v, u) : v;
    int  k1  = in2 ? (v00 + 18) : (v00 + 17);
    int  k2  = in2 ? (v00 + 1)  : (v00 + 18);
    float b0 = __fsub_rn(__fsub_rn(1.0f, s), t);

    float2 w0 = w[v00];
    float2 w1 = w[k1];
    float2 w2 = w[k2];

    float rx = __fadd_rn(__fadd_rn(__fmul_rn(b0, w0.x), __fmul_rn(s, w1.x)),
                         __fmul_rn(t, w2.x));
    float ry = __fadd_rn(__fadd_rn(__fmul_rn(b0, w0.y), __fmul_rn(s, w1.y)),
                         __fmul_rn(t, w2.y));
    ox = hit ? rx : 0.0f;
    oy = hit ? ry : 0.0f;
}

__global__ void __launch_bounds__(256)
p1_eval_kernel(const float2* __restrict__ pts,
               const float*  __restrict__ wx,
               const float*  __restrict__ wy,
               float2* __restrict__ out)
{
    __shared__ float2 wsh[289];

    int tid = threadIdx.x;
    int gid = blockIdx.x * blockDim.x + tid;

    // issue the (independent) point load first so its L2/DRAM trip overlaps
    // the smem weight fill
    float2 p = pts[gid];

    // vectorized weight stage: threads 0..71 move 4 (wx,wy) pairs each,
    // thread 72 the 289th element
    if (tid < 72) {
        float4 a = __ldg((const float4*)wx + tid);
        float4 b = __ldg((const float4*)wy + tid);
        int base = tid * 4;
        wsh[base + 0] = make_float2(a.x, b.x);
        wsh[base + 1] = make_float2(a.y, b.y);
        wsh[base + 2] = make_float2(a.z, b.z);
        wsh[base + 3] = make_float2(a.w, b.w);
    } else if (tid == 72) {
        wsh[288] = make_float2(__ldg(wx + 288), __ldg(wy + 288));
    }
    __syncthreads();

    float2 r;
    eval_point(p.x, p.y, wsh, r.x, r.y);
    out[gid] = r;
}

extern "C" void kernel_launch(void* const* d_in, const int* in_sizes, int n_in,
                              void* d_out, int out_size)
{
    const float2* pts = (const float2*)d_in[0];
    const float*  wx  = (const float*)d_in[1];
    const float*  wy  = (const float*)d_in[2];
    float2* out = (float2*)d_out;

    int n_pts = in_sizes[0] / 2;   // 65536
    int threads = 256;
    int blocks = n_pts / threads;  // 256
    p1_eval_kernel<<<blocks, threads>>>(pts, wx, wy, out);
}

// round 10
// speedup vs baseline: 1.0047x; 1.0047x over previous
#include <cuda_runtime.h>

// P1 vector FEM eval on structured 16x16 triangulated unit square.
// Bit-faithful numerics (R4): exact fp32 classification, interior-gridline
// bbox exclusion, argmax tie -> upper triangle, reference op-order output.
//
// Perf (R10 = measured-best union across R4-R9 sweep):
//   - 128 CTAs x 256 threads, 2 points/thread via float4 LDG/STG
//     (1024 warps; float4 I/O worth ~0.4us over float2 -- R5 vs R4/R9)
//   - weights staged in smem as interleaved (wx,wy) float2 pairs
//     (smem broadcast beats scattered LDG gathers by ~0.6us -- R5 vs R6)
//   - vectorized float4 weight fill: 73 active threads, fast BAR release
// Kernel sits on the launch-overhead floor (~4.4us, all pipes <3%).

__device__ __forceinline__ void eval_point(
    float px, float py, const float2* __restrict__ w, float& ox, float& oy)
{
    const float NTOL = -1e-10f;

    float fx = __fmul_rn(px, 16.0f);    // exact
    float fy = __fmul_rn(py, 16.0f);
    int i = (int)floorf(fx);
    int j = (int)floorf(fy);
    i = min(max(i, 0), 15);
    j = min(max(j, 0), 15);

    float u = __fsub_rn(fx, (float)i);  // exact
    float v = __fsub_rn(fy, (float)j);  // exact

    // reference-faithful inside tests (exact fp32)
    float P  = __fsub_rn(fx, fy);                 // fl(16px - 16py)
    float s1 = __fsub_rn(P, (float)(i - j));      // T1 s
    float t2 = -s1;                               // T2 t (bitwise)

    bool in1 = (s1 > NTOL) && (v > NTOL) && (__fadd_rn(s1, v) < 1.0f);
    bool in2 = (u  > NTOL) && (t2 > NTOL) && (__fadd_rn(u, t2) < 1.0f);

    // interior gridline points fail every strict bbox in the reference
    bool on_g = ((u == 0.0f) && (i > 0)) || ((v == 0.0f) && (j > 0));
    bool hit = (px >= 0.0f) && (px < 1.0f) && (py >= 0.0f) && (py < 1.0f) &&
               !on_g && (in1 || in2);

    // branchless triangle select (argmax tie -> T2)
    int v00 = i * 17 + j;
    float s  = in2 ? u : __fsub_rn(u, v);
    float t  = in2 ? __fsub_rn(v, u) : v;
    int  k1  = in2 ? (v00 + 18) : (v00 + 17);
    int  k2  = in2 ? (v00 + 1)  : (v00 + 18);
    float b0 = __fsub_rn(__fsub_rn(1.0f, s), t);

    float2 w0 = w[v00];
    float2 w1 = w[k1];
    float2 w2 = w[k2];

    float rx = __fadd_rn(__fadd_rn(__fmul_rn(b0, w0.x), __fmul_rn(s, w1.x)),
                         __fmul_rn(t, w2.x));
    float ry = __fadd_rn(__fadd_rn(__fmul_rn(b0, w0.y), __fmul_rn(s, w1.y)),
                         __fmul_rn(t, w2.y));
    ox = hit ? rx : 0.0f;
    oy = hit ? ry : 0.0f;
}

__global__ void __launch_bounds__(256)
p1_eval_kernel(const float4* __restrict__ pts4,
               const float*  __restrict__ wx,
               const float*  __restrict__ wy,
               float4* __restrict__ out4)
{
    __shared__ float2 wsh[289];

    int tid = threadIdx.x;
    int gid = blockIdx.x * blockDim.x + tid;

    // issue the (independent) point load first so its L2/DRAM trip overlaps
    // the smem weight fill
    float4 pp = pts4[gid];   // two points: (x0,y0,x1,y1)

    // vectorized weight stage: threads 0..71 move 4 (wx,wy) pairs each,
    // thread 72 the 289th element
    if (tid < 72) {
        float4 a = __ldg((const float4*)wx + tid);
        float4 b = __ldg((const float4*)wy + tid);
        int base = tid * 4;
        wsh[base + 0] = make_float2(a.x, b.x);
        wsh[base + 1] = make_float2(a.y, b.y);
        wsh[base + 2] = make_float2(a.z, b.z);
        wsh[base + 3] = make_float2(a.w, b.w);
    } else if (tid == 72) {
        wsh[288] = make_float2(__ldg(wx + 288), __ldg(wy + 288));
    }
    __syncthreads();

    float4 r;
    eval_point(pp.x, pp.y, wsh, r.x, r.y);
    eval_point(pp.z, pp.w, wsh, r.z, r.w);

    out4[gid] = r;
}

extern "C" void kernel_launch(void* const* d_in, const int* in_sizes, int n_in,
                              void* d_out, int out_size)
{
    const float4* pts4 = (const float4*)d_in[0];
    const float*  wx   = (const float*)d_in[1];
    const float*  wy   = (const float*)d_in[2];
    float4* out4 = (float4*)d_out;

    // 65536 points -> 32768 float4 -> 128 blocks x 256 threads (one wave)
    int n4 = (in_sizes[0] / 2) / 2;
    int threads = 256;
    int blocks = n4 / threads;     // 128
    p1_eval_kernel<<<blocks, threads>>>(pts4, wx, wy, out4);
}

// round 11
// speedup vs baseline: 1.0386x; 1.0338x over previous
#include <cuda_runtime.h>

// P1 vector FEM eval on structured 16x16 triangulated unit square.
// Bit-faithful numerics (R4): exact fp32 classification, interior-gridline
// bbox exclusion, argmax tie -> upper triangle, reference op-order output.
//
// Perf (R11 = exact R5, the measured optimum of the R4-R10 sweep):
//   - 128 CTAs x 256 threads, 2 points/thread via float4 LDG/STG
//   - weights staged in smem as interleaved (wx,wy) float2 pairs,
//     SPREAD fill (1 pair/thread across all 8 warps -> parallel fill
//     latency; R10 showed 3-warp vectorized fill serializes the bar wait)
//   - branchless triangle select
// Kernel sits on the launch-overhead floor (~4.5us, all pipes <3%).

__device__ __forceinline__ void eval_point(
    float px, float py, const float2* __restrict__ w, float& ox, float& oy)
{
    const float NTOL = -1e-10f;

    float fx = __fmul_rn(px, 16.0f);    // exact
    float fy = __fmul_rn(py, 16.0f);
    int i = (int)floorf(fx);
    int j = (int)floorf(fy);
    i = min(max(i, 0), 15);
    j = min(max(j, 0), 15);

    float u = __fsub_rn(fx, (float)i);  // exact
    float v = __fsub_rn(fy, (float)j);  // exact

    // reference-faithful inside tests (exact fp32)
    float P  = __fsub_rn(fx, fy);                 // fl(16px - 16py)
    float s1 = __fsub_rn(P, (float)(i - j));      // T1 s
    float t2 = -s1;                               // T2 t (bitwise)

    bool in1 = (s1 > NTOL) && (v > NTOL) && (__fadd_rn(s1, v) < 1.0f);
    bool in2 = (u  > NTOL) && (t2 > NTOL) && (__fadd_rn(u, t2) < 1.0f);

    // interior gridline points fail every strict bbox in the reference
    bool on_g = ((u == 0.0f) && (i > 0)) || ((v == 0.0f) && (j > 0));
    bool hit = (px >= 0.0f) && (px < 1.0f) && (py >= 0.0f) && (py < 1.0f) &&
               !on_g && (in1 || in2);

    // branchless triangle select (argmax tie -> T2)
    int v00 = i * 17 + j;
    float s  = in2 ? u : __fsub_rn(u, v);
    float t  = in2 ? __fsub_rn(v, u) : v;
    int  k1  = in2 ? (v00 + 18) : (v00 + 17);
    int  k2  = in2 ? (v00 + 1)  : (v00 + 18);
    float b0 = __fsub_rn(__fsub_rn(1.0f, s), t);

    float2 w0 = w[v00];
    float2 w1 = w[k1];
    float2 w2 = w[k2];

    float rx = __fadd_rn(__fadd_rn(__fmul_rn(b0, w0.x), __fmul_rn(s, w1.x)),
                         __fmul_rn(t, w2.x));
    float ry = __fadd_rn(__fadd_rn(__fmul_rn(b0, w0.y), __fmul_rn(s, w1.y)),
                         __fmul_rn(t, w2.y));
    ox = hit ? rx : 0.0f;
    oy = hit ? ry : 0.0f;
}

__global__ void __launch_bounds__(256)
p1_eval_kernel(const float4* __restrict__ pts4,
               const float*  __restrict__ wx,
               const float*  __restrict__ wy,
               float4* __restrict__ out4)
{
    __shared__ float2 wsh[289];

    int tid = threadIdx.x;
    int gid = blockIdx.x * blockDim.x + tid;

    // issue the (independent) point load first so it overlaps the smem fill
    float4 pp = pts4[gid];   // two points: (x0,y0,x1,y1)

    // spread weight stage: 1 (wx,wy) pair per thread across all warps
    if (tid < 289)       wsh[tid]       = make_float2(__ldg(wx + tid),
                                                      __ldg(wy + tid));
    int t2i = tid + 256;
    if (t2i < 289)       wsh[t2i]       = make_float2(__ldg(wx + t2i),
                                                      __ldg(wy + t2i));
    __syncthreads();

    float4 r;
    eval_point(pp.x, pp.y, wsh, r.x, r.y);
    eval_point(pp.z, pp.w, wsh, r.z, r.w);

    out4[gid] = r;
}

extern "C" void kernel_launch(void* const* d_in, const int* in_sizes, int n_in,
                              void* d_out, int out_size)
{
    const float4* pts4 = (const float4*)d_in[0];
    const float*  wx   = (const float*)d_in[1];
    const float*  wy   = (const float*)d_in[2];
    float4* out4 = (float4*)d_out;

    // 65536 points -> 32768 float4 -> 128 blocks x 256 threads (one wave)
    int n4 = (in_sizes[0] / 2) / 2;
    int threads = 256;
    int blocks = n4 / threads;     // 128
    p1_eval_kernel<<<blocks, threads>>>(pts4, wx, wy, out4);
}